// round 14
// baseline (speedup 1.0000x reference)
#include <cuda_runtime.h>
#include <cuda_fp16.h>
#include <cstdint>

#define NR   4096
#define DD   512
#define BM   128
#define KSZ  64                  // k floats per stage chunk (128B fp16 rows)
#define NCHUNK 8                 // DD / KSZ
#define NSTG 3
#define NTH  256
#define NBLK (NR / BM)                      // 32
#define NTILES (NBLK * (NBLK + 1) / 2)      // 528
#define STAGE_BYTES 32768        // A 16K | B 16K
#define SMEM_LABELS (NSTG * STAGE_BYTES)    // 98304
#define SMEM_TOTAL  (SMEM_LABELS + 1024)
#define MARGIN 40.0f

// ---------------- device scratch ----------------
__device__ __half g_hf[NR * DD];
__device__ unsigned g_min_enc[NR];
__device__ unsigned g_max_enc[NR];

// ---------------- helpers ----------------
__device__ __forceinline__ unsigned enc_f(float f) {
    unsigned u = __float_as_uint(f);
    return (u & 0x80000000u) ? ~u : (u | 0x80000000u);
}
__device__ __forceinline__ float dec_f(unsigned e) {
    unsigned u = (e & 0x80000000u) ? (e ^ 0x80000000u) : ~e;
    return __uint_as_float(u);
}
__device__ __forceinline__ uint32_t smem_u32(const void* p) {
    uint32_t a;
    asm("{ .reg .u64 t; cvta.to.shared.u64 t, %1; cvt.u32.u64 %0, t; }" : "=r"(a) : "l"(p));
    return a;
}

#define CP16(smem_addr, gptr) \
    asm volatile("cp.async.cg.shared.global [%0], [%1], 16;" :: "r"(smem_addr), "l"(gptr))
#define CP_COMMIT() asm volatile("cp.async.commit_group;" ::: "memory")
#define CP_WAIT(n)  asm volatile("cp.async.wait_group %0;" :: "n"(n) : "memory")

#define LDSM4(r, addr) \
    asm volatile("ldmatrix.sync.aligned.m8n8.x4.shared.b16 {%0,%1,%2,%3}, [%4];" \
                 : "=r"((r)[0]), "=r"((r)[1]), "=r"((r)[2]), "=r"((r)[3]) : "r"(addr))

// f16-accumulate HMMA: d/c are 2 b16x2 regs holding {c0,c1},{c2,c3}
#define MMA_F16ACC(d, a, b0, b1) \
    asm volatile("mma.sync.aligned.m16n8k16.row.col.f16.f16.f16.f16 " \
                 "{%0,%1}, {%2,%3,%4,%5}, {%6,%7}, {%0,%1};" \
                 : "+r"((d)[0]), "+r"((d)[1]) \
                 : "r"((a)[0]), "r"((a)[1]), "r"((a)[2]), "r"((a)[3]), "r"(b0), "r"(b1))

// full SW128 swizzle for 128B rows: chunk c in {0..7} (16B each), row r
__device__ __forceinline__ uint32_t sw128(int r, int c) {
    return (uint32_t)(r * 128 + ((c ^ (r & 7)) << 4));
}

// ---------------- convert + init fused ----------------
__global__ void split_kernel(const float* __restrict__ feat) {
    const int base = blockIdx.x * (256 * 4) + threadIdx.x;   // 512 blocks
    int gi = blockIdx.x * 256 + threadIdx.x;
    if (gi < NR) {
        g_min_enc[gi] = enc_f(3.402823466e38f);
        g_max_enc[gi] = enc_f(-3.402823466e38f);
    }
    float4 v[4];
#pragma unroll
    for (int k = 0; k < 4; k++)
        v[k] = ((const float4*)feat)[base + k * 256];
#pragma unroll
    for (int k = 0; k < 4; k++) {
        __half2 h0 = __floats2half2_rn(v[k].x, v[k].y);
        __half2 h1 = __floats2half2_rn(v[k].z, v[k].w);
        uint2 pk;
        pk.x = *(uint32_t*)&h0;
        pk.y = *(uint32_t*)&h1;
        ((uint2*)g_hf)[base + k * 256] = pk;
    }
}

__global__ __launch_bounds__(NTH, 2)
void corr_kernel(const int* __restrict__ targets) {
    extern __shared__ char smem[];
    const uint32_t sb = smem_u32(smem);
    int* ti_s = (int*)(smem + SMEM_LABELS);
    int* tj_s = ti_s + BM;

    // ---- triangular tile decode: tiles with bj >= bi ----
    const int t = blockIdx.x;
    int bi = (int)((65.0f - sqrtf(4225.0f - 8.0f * (float)t)) * 0.5f);
    while (32 * bi - (bi * (bi - 1)) / 2 > t) bi--;
    while (32 * (bi + 1) - ((bi + 1) * bi) / 2 <= t) bi++;
    const int bj = bi + (t - (32 * bi - (bi * (bi - 1)) / 2));
    const int i0 = bi * BM;
    const int j0 = bj * BM;
    const bool diag = (bi == bj);

    const int tid  = threadIdx.x;
    const int lane = tid & 31;
    const int wid  = tid >> 5;
    const int wm   = wid & 1;    // 0..1  (64-row band)
    const int wn   = wid >> 1;   // 0..3  (32-col band)

    if (tid < BM) ti_s[tid] = targets[i0 + tid];
    else          tj_s[tid - BM] = targets[j0 + (tid - BM)];

    // two f16x2 accumulator groups: [half][mt][nt][2regs] — 64 regs total
    uint32_t acch[2][4][4][2];
#pragma unroll
    for (int g = 0; g < 2; g++)
#pragma unroll
        for (int mt = 0; mt < 4; mt++)
#pragma unroll
            for (int nt = 0; nt < 4; nt++) {
                acch[g][mt][nt][0] = 0u;
                acch[g][mt][nt][1] = 0u;
            }

    // --- pipeline: 8 chunks of k=64; stage carries A(16K) | B(16K) ---
#define ISSUE(s) do {                                                          \
    int k0 = (s) * KSZ;                                                        \
    uint32_t sbase = sb + ((s) % NSTG) * STAGE_BYTES;                          \
    _Pragma("unroll")                                                          \
    for (int it = 0; it < 4; it++) {                                           \
        int lin = tid + it * NTH;        /* 0..1023 */                         \
        int r   = lin >> 3;                                                    \
        int c   = lin & 7;                                                     \
        uint32_t so = sw128(r, c);                                             \
        CP16(sbase + so,         g_hf + (size_t)(i0 + r) * DD + k0 + c * 8);   \
        CP16(sbase + 16384 + so, g_hf + (size_t)(j0 + r) * DD + k0 + c * 8);   \
    }                                                                          \
    CP_COMMIT();                                                               \
} while (0)

    ISSUE(0); ISSUE(1);

    for (int s = 0; s < NCHUNK; s++) {
        CP_WAIT(1);
        __syncthreads();
        if (s + 2 < NCHUNK) ISSUE(s + 2);

        const uint32_t st = sb + (s % NSTG) * STAGE_BYTES;
        const int g = s >> 2;    // accumulator group: chunks 0-3 -> 0, 4-7 -> 1
#pragma unroll
        for (int kk = 0; kk < 4; kk++) {
            uint32_t bfr[2][4];
#pragma unroll
            for (int nt2 = 0; nt2 < 2; nt2++) {
                int n = wn * 32 + nt2 * 16 + (lane & 7) + ((lane >> 4) << 3);
                int c = kk * 2 + ((lane >> 3) & 1);
                LDSM4(bfr[nt2], st + 16384 + sw128(n, c));
            }
#pragma unroll
            for (int mt = 0; mt < 4; mt++) {
                uint32_t a[4];
                int r = wm * 64 + mt * 16 + (lane & 15);
                int c = kk * 2 + (lane >> 4);
                LDSM4(a, st + sw128(r, c));
#pragma unroll
                for (int nt = 0; nt < 4; nt++) {
                    uint32_t b0 = bfr[nt >> 1][(nt & 1) * 2];
                    uint32_t b1 = bfr[nt >> 1][(nt & 1) * 2 + 1];
                    if (g == 0) MMA_F16ACC(acch[0][mt][nt], a, b0, b1);
                    else        MMA_F16ACC(acch[1][mt][nt], a, b0, b1);
                }
            }
        }
    }

    // ---- epilogue: combine halves in f32, fold masked min/max ----
    int clsr[4][2], clsc[4][2];
#pragma unroll
    for (int mt = 0; mt < 4; mt++)
#pragma unroll
        for (int h = 0; h < 2; h++)
            clsr[mt][h] = ti_s[wm * 64 + mt * 16 + (lane >> 2) + h * 8];
#pragma unroll
    for (int nt = 0; nt < 4; nt++)
#pragma unroll
        for (int p = 0; p < 2; p++)
            clsc[nt][p] = tj_s[wn * 32 + nt * 8 + (lane & 3) * 2 + p];

    float rmin[4][2], rmax[4][2], cmin[4][2], cmax[4][2];
#pragma unroll
    for (int a2 = 0; a2 < 4; a2++)
#pragma unroll
        for (int b2 = 0; b2 < 2; b2++) {
            rmin[a2][b2] = 3.402823466e38f;  rmax[a2][b2] = -3.402823466e38f;
            cmin[a2][b2] = 3.402823466e38f;  cmax[a2][b2] = -3.402823466e38f;
        }

#pragma unroll
    for (int mt = 0; mt < 4; mt++)
#pragma unroll
        for (int nt = 0; nt < 4; nt++) {
            float2 lo0 = __half22float2(*(__half2*)&acch[0][mt][nt][0]);
            float2 hi0 = __half22float2(*(__half2*)&acch[0][mt][nt][1]);
            float2 lo1 = __half22float2(*(__half2*)&acch[1][mt][nt][0]);
            float2 hi1 = __half22float2(*(__half2*)&acch[1][mt][nt][1]);
            float vv[4];
            vv[0] = lo0.x + lo1.x;   // h=0, p=0
            vv[1] = lo0.y + lo1.y;   // h=0, p=1
            vv[2] = hi0.x + hi1.x;   // h=1, p=0
            vv[3] = hi0.y + hi1.y;   // h=1, p=1
#pragma unroll
            for (int h = 0; h < 2; h++)
#pragma unroll
                for (int p = 0; p < 2; p++) {
                    float v = vv[h * 2 + p];
                    if (clsr[mt][h] == clsc[nt][p]) {
                        rmin[mt][h] = fminf(rmin[mt][h], v);
                        cmin[nt][p] = fminf(cmin[nt][p], v);
                    } else {
                        rmax[mt][h] = fmaxf(rmax[mt][h], v);
                        cmax[nt][p] = fmaxf(cmax[nt][p], v);
                    }
                }
        }

    // row reduction across the 4 lanes of each quad-row group (xor 1, 2)
#pragma unroll
    for (int mt = 0; mt < 4; mt++)
#pragma unroll
        for (int h = 0; h < 2; h++) {
            float vmin = rmin[mt][h], vmax = rmax[mt][h];
#pragma unroll
            for (int off = 1; off < 4; off <<= 1) {
                vmin = fminf(vmin, __shfl_xor_sync(0xffffffffu, vmin, off));
                vmax = fmaxf(vmax, __shfl_xor_sync(0xffffffffu, vmax, off));
            }
            if ((lane & 3) == 0) {
                int rl = wm * 64 + mt * 16 + (lane >> 2) + h * 8;
                atomicMin(&g_min_enc[i0 + rl], enc_f(vmin));
                atomicMax(&g_max_enc[i0 + rl], enc_f(vmax));
            }
        }

    // column reduction across the 8 row-groups (xor 4, 8, 16) — off-diagonal only
    if (!diag) {
#pragma unroll
        for (int nt = 0; nt < 4; nt++)
#pragma unroll
            for (int p = 0; p < 2; p++) {
                float vmin = cmin[nt][p], vmax = cmax[nt][p];
#pragma unroll
                for (int off = 4; off < 32; off <<= 1) {
                    vmin = fminf(vmin, __shfl_xor_sync(0xffffffffu, vmin, off));
                    vmax = fmaxf(vmax, __shfl_xor_sync(0xffffffffu, vmax, off));
                }
                if ((lane >> 2) == 0) {
                    int cl = wn * 32 + nt * 8 + (lane & 3) * 2 + p;
                    atomicMin(&g_min_enc[j0 + cl], enc_f(vmin));
                    atomicMax(&g_max_enc[j0 + cl], enc_f(vmax));
                }
            }
    }
#undef ISSUE
}

__global__ void loss_kernel(float* __restrict__ out) {
    __shared__ float red[1024];
    const int t = threadIdx.x;
    uint4 mn = ((const uint4*)g_min_enc)[t];
    uint4 mx = ((const uint4*)g_max_enc)[t];
    float s = 0.0f, v;
    v = dec_f(mx.x) - dec_f(mn.x) + MARGIN; s += fmaxf(v, 0.0f);
    v = dec_f(mx.y) - dec_f(mn.y) + MARGIN; s += fmaxf(v, 0.0f);
    v = dec_f(mx.z) - dec_f(mn.z) + MARGIN; s += fmaxf(v, 0.0f);
    v = dec_f(mx.w) - dec_f(mn.w) + MARGIN; s += fmaxf(v, 0.0f);
    red[t] = s;
    __syncthreads();
    for (int o = 512; o > 32; o >>= 1) {
        if (t < o) red[t] += red[t + o];
        __syncthreads();
    }
    if (t < 32) {
        float x = red[t] + red[t + 32];
#pragma unroll
        for (int off = 16; off > 0; off >>= 1)
            x += __shfl_xor_sync(0xffffffffu, x, off);
        if (t == 0) out[0] = x * (1.0f / (float)NR);
    }
}

// ---------------- launch ----------------
extern "C" void kernel_launch(void* const* d_in, const int* in_sizes, int n_in,
                              void* d_out, int out_size) {
    const float* feat    = (const float*)d_in[0];
    const int*   targets = (const int*)d_in[1];
    float*       out     = (float*)d_out;

    cudaFuncSetAttribute(corr_kernel, cudaFuncAttributeMaxDynamicSharedMemorySize,
                         SMEM_TOTAL);

    split_kernel<<<512, 256>>>(feat);
    corr_kernel<<<NTILES, NTH, SMEM_TOTAL>>>(targets);
    loss_kernel<<<1, 1024>>>(out);
}

// round 15
// speedup vs baseline: 1.3847x; 1.3847x over previous
#include <cuda_runtime.h>
#include <cuda_fp16.h>
#include <cstdint>

#define NR   4096
#define DD   512
#define BM   128
#define KSZ  64                  // k floats per stage chunk (128B fp16 rows)
#define NCHUNK 8                 // DD / KSZ
#define NSTG 3
#define NTH  256
#define NBLK (NR / BM)                      // 32
#define NTILES (NBLK * (NBLK + 1) / 2)      // 528
#define STAGE_BYTES 32768        // A 16K | B 16K
#define SMEM_LABELS (NSTG * STAGE_BYTES)    // 98304
#define SMEM_TOTAL  (SMEM_LABELS + 1024)
#define MARGIN 40.0f

// ---------------- device scratch ----------------
__device__ __half g_hf[NR * DD];
__device__ unsigned g_min_enc[NR];
__device__ unsigned g_max_enc[NR];

// ---------------- helpers ----------------
__device__ __forceinline__ unsigned enc_f(float f) {
    unsigned u = __float_as_uint(f);
    return (u & 0x80000000u) ? ~u : (u | 0x80000000u);
}
__device__ __forceinline__ float dec_f(unsigned e) {
    unsigned u = (e & 0x80000000u) ? (e ^ 0x80000000u) : ~e;
    return __uint_as_float(u);
}
__device__ __forceinline__ uint32_t smem_u32(const void* p) {
    uint32_t a;
    asm("{ .reg .u64 t; cvta.to.shared.u64 t, %1; cvt.u32.u64 %0, t; }" : "=r"(a) : "l"(p));
    return a;
}

#define CP16(smem_addr, gptr) \
    asm volatile("cp.async.cg.shared.global [%0], [%1], 16;" :: "r"(smem_addr), "l"(gptr))
#define CP_COMMIT() asm volatile("cp.async.commit_group;" ::: "memory")
#define CP_WAIT(n)  asm volatile("cp.async.wait_group %0;" :: "n"(n) : "memory")

#define LDSM4(r, addr) \
    asm volatile("ldmatrix.sync.aligned.m8n8.x4.shared.b16 {%0,%1,%2,%3}, [%4];" \
                 : "=r"((r)[0]), "=r"((r)[1]), "=r"((r)[2]), "=r"((r)[3]) : "r"(addr))

#define MMA_F16(d, a, b0, b1) \
    asm volatile("mma.sync.aligned.m16n8k16.row.col.f32.f16.f16.f32 " \
                 "{%0,%1,%2,%3}, {%4,%5,%6,%7}, {%8,%9}, {%0,%1,%2,%3};" \
                 : "+f"((d)[0]), "+f"((d)[1]), "+f"((d)[2]), "+f"((d)[3]) \
                 : "r"((a)[0]), "r"((a)[1]), "r"((a)[2]), "r"((a)[3]), "r"(b0), "r"(b1))

// full SW128 swizzle for 128B rows: chunk c in {0..7} (16B each), row r
__device__ __forceinline__ uint32_t sw128(int r, int c) {
    return (uint32_t)(r * 128 + ((c ^ (r & 7)) << 4));
}

// ---------------- convert + init fused ----------------
__global__ void split_kernel(const float* __restrict__ feat) {
    const int base = blockIdx.x * (256 * 4) + threadIdx.x;   // 512 blocks
    int gi = blockIdx.x * 256 + threadIdx.x;
    if (gi < NR) {
        g_min_enc[gi] = enc_f(3.402823466e38f);
        g_max_enc[gi] = enc_f(-3.402823466e38f);
    }
    float4 v[4];
#pragma unroll
    for (int k = 0; k < 4; k++)
        v[k] = ((const float4*)feat)[base + k * 256];
#pragma unroll
    for (int k = 0; k < 4; k++) {
        __half2 h0 = __floats2half2_rn(v[k].x, v[k].y);
        __half2 h1 = __floats2half2_rn(v[k].z, v[k].w);
        uint2 pk;
        pk.x = *(uint32_t*)&h0;
        pk.y = *(uint32_t*)&h1;
        ((uint2*)g_hf)[base + k * 256] = pk;
    }
}

__global__ __launch_bounds__(NTH, 2)
void corr_kernel(const int* __restrict__ targets) {
    extern __shared__ char smem[];
    const uint32_t sb = smem_u32(smem);
    int* ti_s = (int*)(smem + SMEM_LABELS);
    int* tj_s = ti_s + BM;

    // ---- triangular tile decode: tiles with bj >= bi ----
    const int t = blockIdx.x;
    int bi = (int)((65.0f - sqrtf(4225.0f - 8.0f * (float)t)) * 0.5f);
    while (32 * bi - (bi * (bi - 1)) / 2 > t) bi--;
    while (32 * (bi + 1) - ((bi + 1) * bi) / 2 <= t) bi++;
    const int bj = bi + (t - (32 * bi - (bi * (bi - 1)) / 2));
    const int i0 = bi * BM;
    const int j0 = bj * BM;
    const bool diag = (bi == bj);

    const int tid  = threadIdx.x;
    const int lane = tid & 31;
    const int wid  = tid >> 5;
    const int wm   = wid & 1;    // 0..1  (64-row band)
    const int wn   = wid >> 1;   // 0..3  (32-col band)

    if (tid < BM) ti_s[tid] = targets[i0 + tid];
    else          tj_s[tid - BM] = targets[j0 + (tid - BM)];

    float acc[4][4][4];
#pragma unroll
    for (int mt = 0; mt < 4; mt++)
#pragma unroll
        for (int nt = 0; nt < 4; nt++)
#pragma unroll
            for (int j = 0; j < 4; j++) acc[mt][nt][j] = 0.0f;

    // --- pipeline: 8 chunks of k=64; stage carries A(16K) | B(16K) ---
#define ISSUE(s) do {                                                          \
    int k0 = (s) * KSZ;                                                        \
    uint32_t sbase = sb + ((s) % NSTG) * STAGE_BYTES;                          \
    _Pragma("unroll")                                                          \
    for (int it = 0; it < 4; it++) {                                           \
        int lin = tid + it * NTH;        /* 0..1023 */                         \
        int r   = lin >> 3;                                                    \
        int c   = lin & 7;                                                     \
        uint32_t so = sw128(r, c);                                             \
        CP16(sbase + so,         g_hf + (size_t)(i0 + r) * DD + k0 + c * 8);   \
        CP16(sbase + 16384 + so, g_hf + (size_t)(j0 + r) * DD + k0 + c * 8);   \
    }                                                                          \
    CP_COMMIT();                                                               \
} while (0)

    ISSUE(0); ISSUE(1);

    for (int s = 0; s < NCHUNK; s++) {
        CP_WAIT(1);
        __syncthreads();
        if (s + 2 < NCHUNK) ISSUE(s + 2);

        const uint32_t st = sb + (s % NSTG) * STAGE_BYTES;
#pragma unroll
        for (int kk = 0; kk < 4; kk++) {
            uint32_t bfr[2][4];
#pragma unroll
            for (int nt2 = 0; nt2 < 2; nt2++) {
                int n = wn * 32 + nt2 * 16 + (lane & 7) + ((lane >> 4) << 3);
                int c = kk * 2 + ((lane >> 3) & 1);
                LDSM4(bfr[nt2], st + 16384 + sw128(n, c));
            }
#pragma unroll
            for (int mt = 0; mt < 4; mt++) {
                uint32_t a[4];
                int r = wm * 64 + mt * 16 + (lane & 15);
                int c = kk * 2 + (lane >> 4);
                LDSM4(a, st + sw128(r, c));
#pragma unroll
                for (int nt = 0; nt < 4; nt++) {
                    uint32_t b0 = bfr[nt >> 1][(nt & 1) * 2];
                    uint32_t b1 = bfr[nt >> 1][(nt & 1) * 2 + 1];
                    MMA_F16(acc[mt][nt], a, b0, b1);
                }
            }
        }
    }

    // ---- epilogue: fold fragments into row (and, off-diag, column) min/max ----
    int clsr[4][2], clsc[4][2];
#pragma unroll
    for (int mt = 0; mt < 4; mt++)
#pragma unroll
        for (int h = 0; h < 2; h++)
            clsr[mt][h] = ti_s[wm * 64 + mt * 16 + (lane >> 2) + h * 8];
#pragma unroll
    for (int nt = 0; nt < 4; nt++)
#pragma unroll
        for (int p = 0; p < 2; p++)
            clsc[nt][p] = tj_s[wn * 32 + nt * 8 + (lane & 3) * 2 + p];

    float rmin[4][2], rmax[4][2], cmin[4][2], cmax[4][2];
#pragma unroll
    for (int a2 = 0; a2 < 4; a2++)
#pragma unroll
        for (int b2 = 0; b2 < 2; b2++) {
            rmin[a2][b2] = 3.402823466e38f;  rmax[a2][b2] = -3.402823466e38f;
            cmin[a2][b2] = 3.402823466e38f;  cmax[a2][b2] = -3.402823466e38f;
        }

#pragma unroll
    for (int mt = 0; mt < 4; mt++)
#pragma unroll
        for (int nt = 0; nt < 4; nt++)
#pragma unroll
            for (int h = 0; h < 2; h++)
#pragma unroll
                for (int p = 0; p < 2; p++) {
                    float v = acc[mt][nt][h * 2 + p];
                    if (clsr[mt][h] == clsc[nt][p]) {
                        rmin[mt][h] = fminf(rmin[mt][h], v);
                        cmin[nt][p] = fminf(cmin[nt][p], v);
                    } else {
                        rmax[mt][h] = fmaxf(rmax[mt][h], v);
                        cmax[nt][p] = fmaxf(cmax[nt][p], v);
                    }
                }

    // row reduction across the 4 lanes of each quad-row group (xor 1, 2)
#pragma unroll
    for (int mt = 0; mt < 4; mt++)
#pragma unroll
        for (int h = 0; h < 2; h++) {
            float vmin = rmin[mt][h], vmax = rmax[mt][h];
#pragma unroll
            for (int off = 1; off < 4; off <<= 1) {
                vmin = fminf(vmin, __shfl_xor_sync(0xffffffffu, vmin, off));
                vmax = fmaxf(vmax, __shfl_xor_sync(0xffffffffu, vmax, off));
            }
            if ((lane & 3) == 0) {
                int rl = wm * 64 + mt * 16 + (lane >> 2) + h * 8;
                atomicMin(&g_min_enc[i0 + rl], enc_f(vmin));
                atomicMax(&g_max_enc[i0 + rl], enc_f(vmax));
            }
        }

    // column reduction across the 8 row-groups (xor 4, 8, 16) — off-diagonal only
    if (!diag) {
#pragma unroll
        for (int nt = 0; nt < 4; nt++)
#pragma unroll
            for (int p = 0; p < 2; p++) {
                float vmin = cmin[nt][p], vmax = cmax[nt][p];
#pragma unroll
                for (int off = 4; off < 32; off <<= 1) {
                    vmin = fminf(vmin, __shfl_xor_sync(0xffffffffu, vmin, off));
                    vmax = fmaxf(vmax, __shfl_xor_sync(0xffffffffu, vmax, off));
                }
                if ((lane >> 2) == 0) {
                    int cl = wn * 32 + nt * 8 + (lane & 3) * 2 + p;
                    atomicMin(&g_min_enc[j0 + cl], enc_f(vmin));
                    atomicMax(&g_max_enc[j0 + cl], enc_f(vmax));
                }
            }
    }
#undef ISSUE
}

__global__ void loss_kernel(float* __restrict__ out) {
    __shared__ float red[1024];
    const int t = threadIdx.x;
    uint4 mn = ((const uint4*)g_min_enc)[t];
    uint4 mx = ((const uint4*)g_max_enc)[t];
    float s = 0.0f, v;
    v = dec_f(mx.x) - dec_f(mn.x) + MARGIN; s += fmaxf(v, 0.0f);
    v = dec_f(mx.y) - dec_f(mn.y) + MARGIN; s += fmaxf(v, 0.0f);
    v = dec_f(mx.z) - dec_f(mn.z) + MARGIN; s += fmaxf(v, 0.0f);
    v = dec_f(mx.w) - dec_f(mn.w) + MARGIN; s += fmaxf(v, 0.0f);
    red[t] = s;
    __syncthreads();
    for (int o = 512; o > 32; o >>= 1) {
        if (t < o) red[t] += red[t + o];
        __syncthreads();
    }
    if (t < 32) {
        float x = red[t] + red[t + 32];
#pragma unroll
        for (int off = 16; off > 0; off >>= 1)
            x += __shfl_xor_sync(0xffffffffu, x, off);
        if (t == 0) out[0] = x * (1.0f / (float)NR);
    }
}

// ---------------- launch ----------------
extern "C" void kernel_launch(void* const* d_in, const int* in_sizes, int n_in,
                              void* d_out, int out_size) {
    const float* feat    = (const float*)d_in[0];
    const int*   targets = (const int*)d_in[1];
    float*       out     = (float*)d_out;

    cudaFuncSetAttribute(corr_kernel, cudaFuncAttributeMaxDynamicSharedMemorySize,
                         SMEM_TOTAL);

    split_kernel<<<512, 256>>>(feat);
    corr_kernel<<<NTILES, NTH, SMEM_TOTAL>>>(targets);
    loss_kernel<<<1, 1024>>>(out);
}